// round 2
// baseline (speedup 1.0000x reference)
#include <cuda_runtime.h>
#include <cuda_bf16.h>
#include <cstdint>

#define BATCH 4
#define CCH   256
#define NSEQ  4096
#define HDIM  128
#define LDP   136                  // padded smem row stride (bf16): 272B, ldmatrix conflict-free
#define TILEE (128*LDP)            // elems per 128-row smem tile

// ---------------- device scratch ----------------
__device__ __align__(16) __nv_bfloat16 g_Ahi[BATCH*NSEQ*HDIM];
__device__ __align__(16) __nv_bfloat16 g_Alo[BATCH*NSEQ*HDIM];
__device__ __align__(16) __nv_bfloat16 g_Bhi[BATCH*NSEQ*HDIM];
__device__ __align__(16) __nv_bfloat16 g_Blo[BATCH*NSEQ*HDIM];
__device__ __align__(16) float         g_diag[BATCH*NSEQ];

// ---------------- helpers ----------------
static __device__ __forceinline__ uint32_t smem_u32(const void* p){
  return (uint32_t)__cvta_generic_to_shared(p);
}
static __device__ __forceinline__ void ldsm4(uint32_t&r0,uint32_t&r1,uint32_t&r2,uint32_t&r3,uint32_t a){
  asm volatile("ldmatrix.sync.aligned.m8n8.x4.shared.b16 {%0,%1,%2,%3}, [%4];"
    : "=r"(r0),"=r"(r1),"=r"(r2),"=r"(r3) : "r"(a));
}
static __device__ __forceinline__ void ldsm4t(uint32_t&r0,uint32_t&r1,uint32_t&r2,uint32_t&r3,uint32_t a){
  asm volatile("ldmatrix.sync.aligned.m8n8.x4.trans.shared.b16 {%0,%1,%2,%3}, [%4];"
    : "=r"(r0),"=r"(r1),"=r"(r2),"=r"(r3) : "r"(a));
}
static __device__ __forceinline__ void mma16816(float* c,
    uint32_t a0,uint32_t a1,uint32_t a2,uint32_t a3,uint32_t b0,uint32_t b1){
  asm volatile("mma.sync.aligned.m16n8k16.row.col.f32.bf16.bf16.f32 "
    "{%0,%1,%2,%3}, {%4,%5,%6,%7}, {%8,%9}, {%0,%1,%2,%3};"
    : "+f"(c[0]),"+f"(c[1]),"+f"(c[2]),"+f"(c[3])
    : "r"(a0),"r"(a1),"r"(a2),"r"(a3),"r"(b0),"r"(b1));
}
static __device__ __forceinline__ uint32_t packbf(float x, float y){
  __nv_bfloat16 a=__float2bfloat16(x), b=__float2bfloat16(y);
  return ((uint32_t)__bfloat16_as_ushort(b)<<16)|(uint32_t)__bfloat16_as_ushort(a);
}
static __device__ __forceinline__ void split_store(__nv_bfloat16* hi, __nv_bfloat16* lo,
                                                   int off, float4 v){
  __nv_bfloat16 h0=__float2bfloat16(v.x),h1=__float2bfloat16(v.y);
  __nv_bfloat16 h2=__float2bfloat16(v.z),h3=__float2bfloat16(v.w);
  uint2 ph, pl;
  ph.x = ((uint32_t)__bfloat16_as_ushort(h1)<<16)|__bfloat16_as_ushort(h0);
  ph.y = ((uint32_t)__bfloat16_as_ushort(h3)<<16)|__bfloat16_as_ushort(h2);
  pl.x = packbf(v.x-__bfloat162float(h0), v.y-__bfloat162float(h1));
  pl.y = packbf(v.z-__bfloat162float(h2), v.w-__bfloat162float(h3));
  *(uint2*)(hi + off) = ph;
  *(uint2*)(lo + off) = pl;
}
static __device__ __forceinline__ void cpa16(void* s, const void* g){
  uint32_t sa = smem_u32(s);
  asm volatile("cp.async.cg.shared.global [%0],[%1],16;"::"r"(sa),"l"(g));
}

// ====================================================================
// Phase 1: mapped[b,n,h] = sum_c X[b,c,n]*W[h,c] + bias[h], bf16x3 split,
// stored as hi/lo bf16 pairs at [b][n][h].
// Warp tile 32(n) x 64(h); A = X^T via ldmatrix.trans; B = W non-trans.
// ====================================================================
__global__ void __launch_bounds__(256) map_kernel(
    const float* __restrict__ Xa, const float* __restrict__ Xb,
    const float* __restrict__ Wa, const float* __restrict__ ba,
    const float* __restrict__ Wb, const float* __restrict__ bb)
{
  extern __shared__ __nv_bfloat16 sm[];
  __nv_bfloat16* sXhi = sm;                // [c:128][LDP]
  __nv_bfloat16* sXlo = sm + TILEE;
  __nv_bfloat16* sWhi = sm + 2*TILEE;      // [h:128][LDP]
  __nv_bfloat16* sWlo = sm + 3*TILEE;

  const int t = threadIdx.x, warp = t>>5, lane = t&31;
  const int ntile = blockIdx.x, b = blockIdx.y, sel = blockIdx.z;
  const float* X    = sel ? Xb : Xa;
  const float* W    = sel ? Wb : Wa;
  const float* bias = sel ? bb : ba;
  __nv_bfloat16* Ohi = sel ? g_Bhi : g_Ahi;
  __nv_bfloat16* Olo = sel ? g_Blo : g_Alo;
  const int n0 = ntile*128;
  const int R  = (warp>>1)*32;       // warp row block (n)
  const int CW = (warp&1)*64;        // warp col block (h)

  float acc[2][8][4];
  #pragma unroll
  for (int a=0;a<2;a++)
    #pragma unroll
    for (int f=0;f<8;f++){acc[a][f][0]=0.f;acc[a][f][1]=0.f;acc[a][f][2]=0.f;acc[a][f][3]=0.f;}

  for (int cc=0; cc<2; cc++){        // two K-chunks of 128 channels
    // X chunk [c:128][n:128], coalesced along n
    const float* src = X + ((size_t)b*CCH + (size_t)cc*128)*NSEQ + n0;
    #pragma unroll
    for (int it=0; it<16; it++){
      int idx = t + it*256;
      int row = idx>>5, c4 = idx&31;
      float4 v = *(const float4*)(src + (size_t)row*NSEQ + (c4<<2));
      split_store(sXhi, sXlo, row*LDP + (c4<<2), v);
    }
    // W chunk [h:128][c:128]
    const float* srcW = W + cc*128;
    #pragma unroll
    for (int it=0; it<16; it++){
      int idx = t + it*256;
      int row = idx>>5, c4 = idx&31;
      float4 v = *(const float4*)(srcW + (size_t)row*CCH + (c4<<2));
      split_store(sWhi, sWlo, row*LDP + (c4<<2), v);
    }
    __syncthreads();

    #pragma unroll
    for (int seg=0; seg<3; seg++){
      const __nv_bfloat16* A  = (seg==2)? sXlo : sXhi;
      const __nv_bfloat16* Bm = (seg==1)? sWlo : sWhi;
      uint32_t ab = smem_u32(A), bbs = smem_u32(Bm);
      #pragma unroll
      for (int kk=0; kk<8; kk++){
        int arow = (kk<<4) + (lane&7) + ((lane>>4)<<3);       // c row in tile
        uint32_t A0[4], A1[4];
        ldsm4t(A0[0],A0[1],A0[2],A0[3],
               ab + (uint32_t)((arow*LDP + R      + (((lane>>3)&1)<<3))<<1));
        ldsm4t(A1[0],A1[1],A1[2],A1[3],
               ab + (uint32_t)((arow*LDP + R + 16 + (((lane>>3)&1)<<3))<<1));
        #pragma unroll
        for (int j=0;j<4;j++){
          int brow = CW + (j<<4) + (lane&15);                  // h row
          uint32_t b0,b1,b2,b3;
          ldsm4(b0,b1,b2,b3, bbs + (uint32_t)((brow*LDP + (kk<<4) + ((lane>>4)<<3))<<1));
          mma16816(acc[0][2*j],   A0[0],A0[1],A0[2],A0[3], b0,b2);
          mma16816(acc[0][2*j+1], A0[0],A0[1],A0[2],A0[3], b1,b3);
          mma16816(acc[1][2*j],   A1[0],A1[1],A1[2],A1[3], b0,b2);
          mma16816(acc[1][2*j+1], A1[0],A1[1],A1[2],A1[3], b1,b3);
        }
      }
    }
    __syncthreads();
  }

  // epilogue: +bias, split hi/lo, store [b][n][h]
  const size_t rowbase = (size_t)b*NSEQ + n0;
  #pragma unroll
  for (int a2=0;a2<2;a2++){
    int row0 = R + a2*16 + (lane>>2);
    #pragma unroll
    for (int f=0; f<8; f++){
      int h = CW + (f<<3) + ((lane&3)<<1);
      float bv0 = bias[h], bv1 = bias[h+1];
      float m00=acc[a2][f][0]+bv0, m01=acc[a2][f][1]+bv1;
      float m10=acc[a2][f][2]+bv0, m11=acc[a2][f][3]+bv1;
      __nv_bfloat16 h00=__float2bfloat16(m00), h01=__float2bfloat16(m01);
      __nv_bfloat16 h10=__float2bfloat16(m10), h11=__float2bfloat16(m11);
      int o0 = (int)((rowbase + row0    )*HDIM) + h;
      int o1 = (int)((rowbase + row0 + 8)*HDIM) + h;
      *(uint32_t*)(Ohi+o0) = ((uint32_t)__bfloat16_as_ushort(h01)<<16)|__bfloat16_as_ushort(h00);
      *(uint32_t*)(Ohi+o1) = ((uint32_t)__bfloat16_as_ushort(h11)<<16)|__bfloat16_as_ushort(h10);
      *(uint32_t*)(Olo+o0) = packbf(m00-__bfloat162float(h00), m01-__bfloat162float(h01));
      *(uint32_t*)(Olo+o1) = packbf(m10-__bfloat162float(h10), m11-__bfloat162float(h11));
    }
  }
}

// ====================================================================
// Phase 2: per row n: rowsum = sum_x exp(S[n,x]), diag = exp(S[n,n])/rowsum,
// S = mapped_a . mapped_b^T (bf16x3, K=128). No max subtraction needed.
// 1 CTA = 128 rows; 32 x-tiles of 128; cp.async double-buffered B tiles.
// ====================================================================
static __device__ __forceinline__ void load_tile_async(
    __nv_bfloat16* dh, __nv_bfloat16* dl,
    const __nv_bfloat16* gh, const __nv_bfloat16* gl, size_t rowbase, int t)
{
  #pragma unroll
  for (int it=0; it<8; it++){
    int idx = t + it*256; int row = idx>>4, ch = idx&15;
    cpa16(dh + row*LDP + (ch<<3), gh + (rowbase+row)*HDIM + (ch<<3));
  }
  #pragma unroll
  for (int it=0; it<8; it++){
    int idx = t + it*256; int row = idx>>4, ch = idx&15;
    cpa16(dl + row*LDP + (ch<<3), gl + (rowbase+row)*HDIM + (ch<<3));
  }
}

__global__ void __launch_bounds__(256,1) attn_kernel()
{
  extern __shared__ __nv_bfloat16 sm[];
  __nv_bfloat16* sAhi = sm;
  __nv_bfloat16* sAlo = sm + TILEE;
  __nv_bfloat16* sBt[2][2] = {{sm+2*TILEE, sm+3*TILEE},{sm+4*TILEE, sm+5*TILEE}};
  __shared__ float sdiag[128];
  __shared__ float srow[128];

  const int t = threadIdx.x, warp = t>>5, lane = t&31;
  const int ntile = blockIdx.x, b = blockIdx.y;
  const int n0 = ntile*128;
  const size_t base = (size_t)b*NSEQ;
  const int R  = (warp>>1)*32;
  const int CW = (warp&1)*64;

  load_tile_async(sAhi, sAlo, g_Ahi, g_Alo, base + n0, t);
  asm volatile("cp.async.commit_group;");
  load_tile_async(sBt[0][0], sBt[0][1], g_Bhi, g_Blo, base, t);
  asm volatile("cp.async.commit_group;");

  const int a_row  = (lane&7) + (((lane>>3)&1)<<3);  // + R (+16)
  const int k_off  = ((lane>>4)<<3);
  const int b_rowL = (lane&15);
  const int cb0    = ((lane&3)<<1);
  float rs[4] = {0.f,0.f,0.f,0.f};

  for (int xt=0; xt<32; xt++){
    int buf = xt&1;
    if (xt+1 < 32){
      load_tile_async(sBt[buf^1][0], sBt[buf^1][1], g_Bhi, g_Blo, base + (size_t)(xt+1)*128, t);
      asm volatile("cp.async.commit_group;");
      asm volatile("cp.async.wait_group 1;");
    } else {
      asm volatile("cp.async.wait_group 0;");
    }
    __syncthreads();

    float acc[2][8][4];
    #pragma unroll
    for (int a=0;a<2;a++)
      #pragma unroll
      for (int f=0;f<8;f++){acc[a][f][0]=0.f;acc[a][f][1]=0.f;acc[a][f][2]=0.f;acc[a][f][3]=0.f;}

    #pragma unroll
    for (int seg=0; seg<3; seg++){
      const __nv_bfloat16* A  = (seg==2)? sAlo : sAhi;
      const __nv_bfloat16* Bm = (seg==1)? sBt[buf][1] : sBt[buf][0];
      uint32_t ab = smem_u32(A), bbs = smem_u32(Bm);
      #pragma unroll
      for (int kk=0; kk<8; kk++){
        uint32_t A0[4], A1[4];
        ldsm4(A0[0],A0[1],A0[2],A0[3],
              ab + (uint32_t)(((R      + a_row)*LDP + (kk<<4) + k_off)<<1));
        ldsm4(A1[0],A1[1],A1[2],A1[3],
              ab + (uint32_t)(((R + 16 + a_row)*LDP + (kk<<4) + k_off)<<1));
        #pragma unroll
        for (int j=0;j<4;j++){
          int brow = CW + (j<<4) + b_rowL;
          uint32_t b0,b1,b2,b3;
          ldsm4(b0,b1,b2,b3, bbs + (uint32_t)((brow*LDP + (kk<<4) + k_off)<<1));
          mma16816(acc[0][2*j],   A0[0],A0[1],A0[2],A0[3], b0,b2);
          mma16816(acc[0][2*j+1], A0[0],A0[1],A0[2],A0[3], b1,b3);
          mma16816(acc[1][2*j],   A1[0],A1[1],A1[2],A1[3], b0,b2);
          mma16816(acc[1][2*j+1], A1[0],A1[1],A1[2],A1[3], b1,b3);
        }
      }
    }

    // exp + row-sum accumulate; capture diagonal
    bool isdiag = (xt == ntile);
    #pragma unroll
    for (int a2=0;a2<2;a2++){
      int r0 = R + a2*16 + (lane>>2);
      #pragma unroll
      for (int f=0; f<8; f++){
        int col = CW + (f<<3) + cb0;
        float e0 = __expf(acc[a2][f][0]);
        float e1 = __expf(acc[a2][f][1]);
        float e2 = __expf(acc[a2][f][2]);
        float e3 = __expf(acc[a2][f][3]);
        rs[a2*2]   += e0 + e1;
        rs[a2*2+1] += e2 + e3;
        if (isdiag){
          if (col   == r0  ) sdiag[r0]   = e0;
          if (col+1 == r0  ) sdiag[r0]   = e1;
          if (col   == r0+8) sdiag[r0+8] = e2;
          if (col+1 == r0+8) sdiag[r0+8] = e3;
        }
      }
    }
    __syncthreads();
  }

  // reduce row sums across the 4-lane column groups
  #pragma unroll
  for (int q=0;q<4;q++){
    rs[q] += __shfl_xor_sync(0xffffffffu, rs[q], 1);
    rs[q] += __shfl_xor_sync(0xffffffffu, rs[q], 2);
  }
  // combine the two column-half warps via smem
  if ((warp&1)==0 && (lane&3)==0){
    int rr = lane>>2;
    #pragma unroll
    for (int q=0;q<4;q++) srow[R + q*8 + rr] = rs[q];
  }
  __syncthreads();
  if ((warp&1)==1 && (lane&3)==0){
    int rr = lane>>2;
    #pragma unroll
    for (int q=0;q<4;q++){
      int row = R + q*8 + rr;
      float tot = srow[row] + rs[q];
      g_diag[base + n0 + row] = sdiag[row] / tot;
    }
  }
}

// ====================================================================
// Phase 3: out_a = diag * input_b ; out_b = diag * input_a  (float4)
// ====================================================================
__global__ void __launch_bounds__(256) scale_kernel(
    const float* __restrict__ Xa, const float* __restrict__ Xb, float* __restrict__ out)
{
  const int NF4 = (BATCH*CCH*NSEQ)/4;   // per-tensor float4 count
  const float4* A4 = (const float4*)Xa;
  const float4* B4 = (const float4*)Xb;
  const float4* D4 = (const float4*)g_diag;
  float4* O = (float4*)out;
  int stride = gridDim.x*blockDim.x;
  for (int i = blockIdx.x*blockDim.x + threadIdx.x; i < 2*NF4; i += stride){
    int sel = (i >= NF4);
    int j = sel ? i - NF4 : i;
    int n4 = j & (NSEQ/4 - 1);
    int bb = (j >> 10) >> 8;            // j/(NSEQ/4)/CCH
    float4 d = D4[(bb<<10) + n4];
    float4 v = sel ? A4[j] : B4[j];
    float4 o; o.x=v.x*d.x; o.y=v.y*d.y; o.z=v.z*d.z; o.w=v.w*d.w;
    O[i] = o;
  }
}

extern "C" void kernel_launch(void* const* d_in, const int* in_sizes, int n_in,
                              void* d_out, int out_size) {
  const float* Xa = (const float*)d_in[0];
  const float* Xb = (const float*)d_in[1];
  const float* Wa = (const float*)d_in[2];
  const float* ba = (const float*)d_in[3];
  const float* Wb = (const float*)d_in[4];
  const float* bb = (const float*)d_in[5];
  float* out = (float*)d_out;

  const int SMEM_A = 4*TILEE*2;   // 139264 B
  const int SMEM_B = 6*TILEE*2;   // 208896 B
  cudaFuncSetAttribute(map_kernel,  cudaFuncAttributeMaxDynamicSharedMemorySize, SMEM_A);
  cudaFuncSetAttribute(attn_kernel, cudaFuncAttributeMaxDynamicSharedMemorySize, SMEM_B);

  dim3 ga(NSEQ/128, BATCH, 2);
  map_kernel<<<ga, 256, SMEM_A>>>(Xa, Xb, Wa, ba, Wb, bb);
  dim3 gb(NSEQ/128, BATCH);
  attn_kernel<<<gb, 256, SMEM_B>>>();
  scale_kernel<<<2048, 256>>>(Xa, Xb, out);
}